// round 14
// baseline (speedup 1.0000x reference)
#include <cuda_runtime.h>

#define NN 512          // batch size
#define DD 128          // feature dim
#define THREADS 512
#define APC 4           // anchors per CTA
#define NCTA (NN / APC) // 128
#define PCAP 520        // posd/pidx row capacity (520 = 8 mod 32 -> bank spread)

typedef unsigned long long ull;

__device__ float g_partial[NCTA];
__device__ float g_count[NCTA];
__device__ int   g_done = 0;   // reset by finalizing CTA each launch

// Margin scalar may arrive as float32 or float64 device scalar.
__device__ __forceinline__ float read_margin(const void* p) {
    if (p == nullptr) return 0.2f;
    float f = *(const float*)p;
    if (f == 0.0f) return 0.0f;
    float af = fabsf(f);
    if (af > 1e-20f && af < 1e6f) return f;
    return (float)(*(const double*)p);
}

// Packed f32x2 ops (Blackwell PTX).
__device__ __forceinline__ void fma2(ull& d, ull a, ull b) {
    asm("fma.rn.f32x2 %0, %1, %2, %0;" : "+l"(d) : "l"(a), "l"(b));
}
__device__ __forceinline__ ull add2(ull a, ull b) {
    ull r;
    asm("add.rn.f32x2 %0, %1, %2;" : "=l"(r) : "l"(a), "l"(b));
    return r;
}
__device__ __forceinline__ float hsum2(ull v) {
    float lo, hi;
    asm("mov.b64 {%0, %1}, %2;" : "=f"(lo), "=f"(hi) : "l"(v));
    return lo + hi;
}
__device__ __forceinline__ ull pack2(float lo, float hi) {
    ull r;
    asm("mov.b64 %0, {%1, %2};" : "=l"(r) : "f"(lo), "f"(hi));
    return r;
}

// ---------------------------------------------------------------------------
// Fused-pass kernel. CTA = 4 consecutive anchors, 512 threads.
//  - compact positive INDICES first (labels only)
//  - stage 1: distances for the ~124 positive rows -> posd (+ margin)
//  - main 8 passes: compute row distance in-register and IMMEDIATELY run the
//    packed relu vs posd (lanes l / l+4 split even/odd slots) -> no d_s,
//    no same_s, one fewer barrier, relu overlaps next pass's fma in the DAG.
//  - last-arriving CTA does the deterministic fp64 final reduction.
// ---------------------------------------------------------------------------
__global__ void __launch_bounds__(THREADS, 1)
fused_triplet_kernel(const float* __restrict__ x, const int* __restrict__ L32,
                     const void* __restrict__ mp, float* __restrict__ out,
                     int out_size)
{
    __shared__ __align__(16) float posd[APC][PCAP];  // d[pos]+m (sorted by j)
    __shared__ int                 pidx[APC][PCAP];  // positive row indices
    __shared__ int                 lab_s[NN];        // 2 KB
    __shared__ int                 np_s[APC];
    __shared__ float               wred[THREADS / 32];
    __shared__ int                 flag_s;

    const int tid  = threadIdx.x;
    const int lane = tid & 31;
    const int wid  = tid >> 5;
    const int sub  = tid & 7;      // slice within 8-lane row group
    const int grp  = tid >> 3;     // row-group id 0..63
    const int ib   = blockIdx.x * APC;
    const float m  = read_margin(mp);

    // ---- label dtype detect (int64 => odd 32-bit words all zero) ----
    if (tid == 0) flag_s = 0;
    __syncthreads();
    if (tid < 256 && L32[2 * tid + 1] != 0) flag_s = 1;  // benign OR-race

    // ---- hoist anchors (+eps) into registers: 4 anchors x 4 float4 slices ----
    ull xw[APC][4][2];             // 64 registers of anchor data
    #pragma unroll
    for (int a = 0; a < APC; a++) {
        const float4* xa = (const float4*)(x + (ib + a) * DD);
        #pragma unroll
        for (int i = 0; i < 4; i++) {
            float4 w = xa[sub + 8 * i];
            xw[a][i][0] = pack2(w.x + 1e-6f, w.y + 1e-6f);
            xw[a][i][1] = pack2(w.z + 1e-6f, w.w + 1e-6f);
        }
    }
    // ---- anchor norms in-register (plain 8-lane butterfly, one-time) ----
    float na0, na1, na2, na3;
    {
        float nv[APC];
        #pragma unroll
        for (int a = 0; a < APC; a++) {
            ull nacc = 0;
            #pragma unroll
            for (int i = 0; i < 4; i++) {
                fma2(nacc, xw[a][i][0], xw[a][i][0]);
                fma2(nacc, xw[a][i][1], xw[a][i][1]);
            }
            float s = hsum2(nacc);
            #pragma unroll
            for (int o = 1; o <= 4; o <<= 1) s += __shfl_xor_sync(0xffffffffu, s, o);
            nv[a] = s;
        }
        na0 = nv[0]; na1 = nv[1]; na2 = nv[2]; na3 = nv[3];
    }

    __syncthreads();               // flag_s valid
    const int is64 = (flag_s == 0);
    lab_s[tid] = is64 ? L32[2 * tid] : L32[tid];
    __syncthreads();               // lab_s valid

    const int La0 = lab_s[ib], La1 = lab_s[ib + 1];
    const int La2 = lab_s[ib + 2], La3 = lab_s[ib + 3];

    // per-lane anchor binding (lane sub -> anchor sub&3; lanes l and l^4 pair)
    const int   al  = sub & 3;
    const float naa = (al == 0) ? na0 : (al == 1) ? na1 : (al == 2) ? na2 : na3;
    const int   Laa = (al == 0) ? La0 : (al == 1) ? La1 : (al == 2) ? La2 : La3;

    // ---- compact POSITIVE INDICES: warp a -> anchor a (ballot, fixed order) ----
    if (wid < APC) {
        const int a = wid, self = ib + a;
        const int Lw = (a == 0) ? La0 : (a == 1) ? La1 : (a == 2) ? La2 : La3;
        int cnt = 0;
        #pragma unroll
        for (int base = 0; base < NN; base += 32) {
            int j = base + lane;
            bool p = (lab_s[j] == Lw) && (j != self);
            unsigned msk = __ballot_sync(0xffffffffu, p);
            if (p) pidx[a][cnt + __popc(msk & ((1u << lane) - 1u))] = j;
            cnt += __popc(msk);
        }
        if (lane < 4) posd[a][cnt + lane] = -1e30f;  // sentinels: exact-0 relu
        if (lane == 0) np_s[a] = cnt;
    }
    __syncthreads();

    const int np0 = np_s[0], np1 = np_s[1], np2 = np_s[2], np3 = np_s[3];
    const int c1 = np0, c2 = np0 + np1, c3 = c2 + np2, P = c3 + np3;
    const int npairs = (((al == 0) ? np0 : (al == 1) ? np1
                        : (al == 2) ? np2 : np3) + 3) >> 2;

    // ---- stage 1: distances for positive rows -> posd (gathered, ~2 passes) ----
    const int nsp = (P + 63) >> 6;
    for (int s = 0; s < nsp; s++) {
        int f = s * 64 + grp;
        if (f >= P) f = P - 1;                 // clamp: duplicate compute, same value
        int a = (f >= c1) + (f >= c2) + (f >= c3);
        int k = f - ((a == 0) ? 0 : (a == 1) ? c1 : (a == 2) ? c2 : c3);
        int j = pidx[a][k];
        const ulonglong2* xr = (const ulonglong2*)(x + j * DD);
        ull sx[4], sy[4];
        #pragma unroll
        for (int i = 0; i < 4; i++) {
            ulonglong2 t = xr[sub + 8 * i];
            sx[i] = t.x; sy[i] = t.y;
        }
        ull nacc = 0, dacc = 0;
        #pragma unroll
        for (int i = 0; i < 4; i++) { fma2(nacc, sx[i], sx[i]); fma2(nacc, sy[i], sy[i]); }
        if (a == 0) {
            #pragma unroll
            for (int i = 0; i < 4; i++) { fma2(dacc, xw[0][i][0], sx[i]); fma2(dacc, xw[0][i][1], sy[i]); }
        } else if (a == 1) {
            #pragma unroll
            for (int i = 0; i < 4; i++) { fma2(dacc, xw[1][i][0], sx[i]); fma2(dacc, xw[1][i][1], sy[i]); }
        } else if (a == 2) {
            #pragma unroll
            for (int i = 0; i < 4; i++) { fma2(dacc, xw[2][i][0], sx[i]); fma2(dacc, xw[2][i][1], sy[i]); }
        } else {
            #pragma unroll
            for (int i = 0; i < 4; i++) { fma2(dacc, xw[3][i][0], sx[i]); fma2(dacc, xw[3][i][1], sy[i]); }
        }
        float nb = hsum2(nacc), dt = hsum2(dacc);
        #pragma unroll
        for (int o = 1; o <= 4; o <<= 1) {
            nb += __shfl_xor_sync(0xffffffffu, nb, o);
            dt += __shfl_xor_sync(0xffffffffu, dt, o);
        }
        if (sub == 0) {
            float nas = (a == 0) ? na0 : (a == 1) ? na1 : (a == 2) ? na2 : na3;
            float d2  = fmaf(-2.f, dt, nas + nb);
            posd[a][k] = sqrtf(fmaxf(d2, 0.f)) + m;
        }
    }
    __syncthreads();

    // ---- main 8 passes: distance in-register + fused packed relu ----
    const ull SMASK = 0x7FFFFFFF7FFFFFFFULL;
    const ull HALF2 = pack2(0.5f, 0.5f);
    const ulonglong2* pv = (const ulonglong2*)&posd[al][0];
    const int qstart = sub >> 2;   // lanes l / l+4 split even/odd slots
    ull acc2 = 0, acc2b = 0;
    #pragma unroll
    for (int pass = 0; pass < 8; pass++) {
        const int r = pass * 64 + grp;
        const ulonglong2* xr = (const ulonglong2*)(x + r * DD);
        ull vx[4], vy[4];
        #pragma unroll
        for (int i = 0; i < 4; i++) {
            ulonglong2 t = xr[sub + 8 * i];   // 128B-contiguous per row group
            vx[i] = t.x; vy[i] = t.y;
        }
        ull nbp = 0, p0 = 0, p1 = 0, p2 = 0, p3 = 0;
        #pragma unroll
        for (int i = 0; i < 4; i++) {
            fma2(nbp, vx[i], vx[i]);       fma2(nbp, vy[i], vy[i]);
            fma2(p0, xw[0][i][0], vx[i]);  fma2(p0, xw[0][i][1], vy[i]);
            fma2(p1, xw[1][i][0], vx[i]);  fma2(p1, xw[1][i][1], vy[i]);
            fma2(p2, xw[2][i][0], vx[i]);  fma2(p2, xw[2][i][1], vy[i]);
            fma2(p3, xw[3][i][0], vx[i]);  fma2(p3, xw[3][i][1], vy[i]);
        }
        float nb = hsum2(nbp);
        float a0 = hsum2(p0), a1 = hsum2(p1), a2 = hsum2(p2), a3 = hsum2(p3);

        // value-pairing butterfly: 7 SHFL; lanes l and l^4 both end with the
        // complete dot for anchor l&3 (proven in R12)
        {
            float w  = (sub & 1) ? a0 : a1;
            float rv = __shfl_xor_sync(0xffffffffu, w, 1);
            if (sub & 1) a1 += rv; else a0 += rv;
            float w2  = (sub & 1) ? a2 : a3;
            float rv2 = __shfl_xor_sync(0xffffffffu, w2, 1);
            if (sub & 1) a3 += rv2; else a2 += rv2;
            nb += __shfl_xor_sync(0xffffffffu, nb, 1);
        }
        float fst = (sub & 1) ? a1 : a0;
        float snd = (sub & 1) ? a3 : a2;
        {
            float w  = (sub & 2) ? fst : snd;
            float rv = __shfl_xor_sync(0xffffffffu, w, 2);
            if (sub & 2) snd += rv; else fst += rv;
            nb += __shfl_xor_sync(0xffffffffu, nb, 2);
        }
        float dot = (sub & 2) ? snd : fst;
        dot += __shfl_xor_sync(0xffffffffu, dot, 4);
        nb  += __shfl_xor_sync(0xffffffffu, nb, 4);

        // fused relu for (anchor al, negative g = r)
        int lj = lab_s[r];                     // broadcast LDS (same addr / group)
        if (lj != Laa) {
            float d2 = fmaf(-2.f, dot, naa + nb);
            float dg = sqrtf(fmaxf(d2, 0.f));  // clamp self-pair cancel
            const ull ndg2 = pack2(-dg, -dg);
            for (int q = qstart; q < npairs; q += 2) {
                ulonglong2 v = pv[q];          // LDS.128, conflict-free spread
                ull t0 = add2(v.x, ndg2);
                ull t1 = add2(v.y, ndg2);
                ull r0 = add2(t0, t0 & SMASK); // 2*relu, exact
                ull r1 = add2(t1, t1 & SMASK);
                fma2(acc2,  r0, HALF2);
                fma2(acc2b, r1, HALF2);
            }
        }
    }
    float acc = hsum2(acc2) + hsum2(acc2b);

    // ---- block reduce (fixed tree) ----
    #pragma unroll
    for (int o = 16; o > 0; o >>= 1) acc += __shfl_xor_sync(0xffffffffu, acc, o);
    if (lane == 0) wred[wid] = acc;
    __syncthreads();
    if (wid == 0) {
        float v = (lane < THREADS / 32) ? wred[lane] : 0.f;
        #pragma unroll
        for (int o = 8; o > 0; o >>= 1) v += __shfl_xor_sync(0xffffffffu, v, o);
        if (lane == 0) {
            g_partial[blockIdx.x] = v;
            float c = (float)np0 * (float)(NN - 1 - np0)
                    + (float)np1 * (float)(NN - 1 - np1)
                    + (float)np2 * (float)(NN - 1 - np2)
                    + (float)np3 * (float)(NN - 1 - np3);
            g_count[blockIdx.x] = c;
            __threadfence();
            int t = atomicAdd(&g_done, 1);
            flag_s = (t == NCTA - 1) ? 1 : 0;   // am I the last CTA?
        }
    }
    __syncthreads();

    // ---- last CTA: deterministic fp64 final reduction ----
    if (flag_s && wid == 0) {
        double sd = 0.0, sc = 0.0;
        for (int k = lane; k < NCTA; k += 32) {
            sd += (double)g_partial[k];
            sc += (double)g_count[k];
        }
        #pragma unroll
        for (int o = 16; o > 0; o >>= 1) {
            sd += __shfl_xor_sync(0xffffffffu, sd, o);
            sc += __shfl_xor_sync(0xffffffffu, sc, o);
        }
        if (lane == 0) {
            out[0] = (float)(sd / sc);
            for (int k = 1; k < out_size; k++) out[k] = 0.f;
            __threadfence();
            g_done = 0;   // reset for next graph replay
        }
    }
}

extern "C" void kernel_launch(void* const* d_in, const int* in_sizes, int n_in,
                              void* d_out, int out_size) {
    const float* x      = (const float*)d_in[0];
    const int*   labels = (const int*)d_in[1];
    const void*  margin = (n_in >= 3) ? d_in[2] : nullptr;

    fused_triplet_kernel<<<NCTA, THREADS>>>(x, labels, margin,
                                            (float*)d_out, out_size);
}

// round 15
// speedup vs baseline: 1.1843x; 1.1843x over previous
#include <cuda_runtime.h>

#define NN 512          // batch size
#define DD 128          // feature dim
#define THREADS 512
#define APC 4           // anchors per CTA
#define NCTA (NN / APC) // 128
#define NPOS (NN + 4)   // posd row + sentinel pad (516: 16B-aligned rows)
#define DPAD 520        // d_s row stride (8 mod 32) -> conflict-free stores

typedef unsigned long long ull;

__device__ float g_partial[NCTA];
__device__ float g_count[NCTA];
__device__ int   g_done = 0;   // reset by finalizing CTA each launch

// Margin scalar may arrive as float32 or float64 device scalar.
__device__ __forceinline__ float read_margin(const void* p) {
    if (p == nullptr) return 0.2f;
    float f = *(const float*)p;
    if (f == 0.0f) return 0.0f;
    float af = fabsf(f);
    if (af > 1e-20f && af < 1e6f) return f;
    return (float)(*(const double*)p);
}

// Packed f32x2 ops (Blackwell PTX).
__device__ __forceinline__ void fma2(ull& d, ull a, ull b) {
    asm("fma.rn.f32x2 %0, %1, %2, %0;" : "+l"(d) : "l"(a), "l"(b));
}
__device__ __forceinline__ ull add2(ull a, ull b) {
    ull r;
    asm("add.rn.f32x2 %0, %1, %2;" : "=l"(r) : "l"(a), "l"(b));
    return r;
}
__device__ __forceinline__ float hsum2(ull v) {
    float lo, hi;
    asm("mov.b64 {%0, %1}, %2;" : "=f"(lo), "=f"(hi) : "l"(v));
    return lo + hi;
}
__device__ __forceinline__ ull pack2(float lo, float hi) {
    ull r;
    asm("mov.b64 %0, {%1, %2};" : "=l"(r) : "f"(lo), "f"(hi));
    return r;
}

// ---------------------------------------------------------------------------
// One fused kernel = R13 (best measured, 16.42us) with Phase B loads widened
// to LDS.128 and dead code removed. CTA = 4 consecutive anchors, 512 threads.
// Phase A: pipelined Gram-identity rows; anchors in registers; 7-SHFL
//          value-pairing butterfly; lane-parallel sqrt+store finalize.
// Phase B: packed f32x2 relu, one LDS.128 per 4 positives.
// Last-arriving CTA does the deterministic fp64 final reduction.
// ---------------------------------------------------------------------------
__global__ void __launch_bounds__(THREADS, 1)
fused_triplet_kernel(const float* __restrict__ x, const int* __restrict__ L32,
                     const void* __restrict__ mp, float* __restrict__ out,
                     int out_size)
{
    __shared__ float                  d_s[APC][DPAD];   // distance rows (padded)
    __shared__ unsigned char          same_s[APC][NN];  // same-label flags, 2 KB
    __shared__ __align__(16) float    posd[APC][NPOS];  // compacted d[pos]+m
    __shared__ int                    lab_s[NN];        // 2 KB
    __shared__ int                    np_s[APC];
    __shared__ float                  wred[THREADS / 32];
    __shared__ int                    flag_s;

    const int tid  = threadIdx.x;
    const int lane = tid & 31;
    const int wid  = tid >> 5;
    const int sub  = tid & 7;      // slice within 8-lane row group
    const int grp  = tid >> 3;     // row-group id 0..63
    const int ib   = blockIdx.x * APC;
    const float m  = read_margin(mp);

    // ---- label dtype detect (int64 => odd 32-bit words all zero) ----
    if (tid == 0) flag_s = 0;
    __syncthreads();
    if (tid < 256 && L32[2 * tid + 1] != 0) flag_s = 1;  // benign OR-race

    // ---- hoist anchors (+eps) into registers: 4 anchors x 4 float4 slices ----
    ull xw[APC][4][2];             // 64 registers of anchor data
    #pragma unroll
    for (int a = 0; a < APC; a++) {
        const float4* xa = (const float4*)(x + (ib + a) * DD);
        #pragma unroll
        for (int i = 0; i < 4; i++) {
            float4 w = xa[sub + 8 * i];
            xw[a][i][0] = pack2(w.x + 1e-6f, w.y + 1e-6f);
            xw[a][i][1] = pack2(w.z + 1e-6f, w.w + 1e-6f);
        }
    }
    // ---- anchor norms in-register (plain 8-lane butterfly, one-time) ----
    float na0, na1, na2, na3;
    {
        float nv[APC];
        #pragma unroll
        for (int a = 0; a < APC; a++) {
            ull nacc = 0;
            #pragma unroll
            for (int i = 0; i < 4; i++) {
                fma2(nacc, xw[a][i][0], xw[a][i][0]);
                fma2(nacc, xw[a][i][1], xw[a][i][1]);
            }
            float s = hsum2(nacc);
            #pragma unroll
            for (int o = 1; o <= 4; o <<= 1) s += __shfl_xor_sync(0xffffffffu, s, o);
            nv[a] = s;
        }
        na0 = nv[0]; na1 = nv[1]; na2 = nv[2]; na3 = nv[3];
    }

    __syncthreads();               // flag_s valid
    const int is64 = (flag_s == 0);
    lab_s[tid] = is64 ? L32[2 * tid] : L32[tid];
    __syncthreads();               // lab_s valid

    // ---- same-label flags once (hoisted out of the pass loop) ----
    {
        int lj = lab_s[tid];
        same_s[0][tid] = (unsigned char)(lj == lab_s[ib + 0]);
        same_s[1][tid] = (unsigned char)(lj == lab_s[ib + 1]);
        same_s[2][tid] = (unsigned char)(lj == lab_s[ib + 2]);
        same_s[3][tid] = (unsigned char)(lj == lab_s[ib + 3]);
    }

    // per-lane anchor norm for the distributed finalize (lane sub -> anchor sub&3)
    const float naa = ((sub & 3) == 0) ? na0 : ((sub & 3) == 1) ? na1
                    : ((sub & 3) == 2) ? na2 : na3;

    // ---- Phase A: pipelined; d^2 = na + nb - 2*dot; 8 passes x 64 rows ----
    ull vx[4], vy[4];              // current pass's row slice (prefetched)
    {
        const ulonglong2* xr = (const ulonglong2*)(x + grp * DD);
        #pragma unroll
        for (int i = 0; i < 4; i++) {
            ulonglong2 t = xr[sub + 8 * i];
            vx[i] = t.x; vy[i] = t.y;
        }
    }
    #pragma unroll
    for (int pass = 0; pass < 8; pass++) {
        const int r = pass * 64 + grp;
        // prefetch next pass FIRST (independent of this pass's math)
        ull nx[4], ny[4];
        if (pass < 7) {
            const ulonglong2* xn = (const ulonglong2*)(x + (r + 64) * DD);
            #pragma unroll
            for (int i = 0; i < 4; i++) {
                ulonglong2 t = xn[sub + 8 * i];
                nx[i] = t.x; ny[i] = t.y;
            }
        }
        // compute with current registers (covers the prefetch latency)
        ull nbp = 0, p0 = 0, p1 = 0, p2 = 0, p3 = 0;
        #pragma unroll
        for (int i = 0; i < 4; i++) {
            fma2(nbp, vx[i], vx[i]);       fma2(nbp, vy[i], vy[i]);
            fma2(p0, xw[0][i][0], vx[i]);  fma2(p0, xw[0][i][1], vy[i]);
            fma2(p1, xw[1][i][0], vx[i]);  fma2(p1, xw[1][i][1], vy[i]);
            fma2(p2, xw[2][i][0], vx[i]);  fma2(p2, xw[2][i][1], vy[i]);
            fma2(p3, xw[3][i][0], vx[i]);  fma2(p3, xw[3][i][1], vy[i]);
        }
        float nb = hsum2(nbp);
        float a0 = hsum2(p0), a1 = hsum2(p1), a2 = hsum2(p2), a3 = hsum2(p3);

        // value-pairing butterfly: 7 SHFL total
        {
            float w  = (sub & 1) ? a0 : a1;
            float rv = __shfl_xor_sync(0xffffffffu, w, 1);
            if (sub & 1) a1 += rv; else a0 += rv;
            float w2  = (sub & 1) ? a2 : a3;
            float rv2 = __shfl_xor_sync(0xffffffffu, w2, 1);
            if (sub & 1) a3 += rv2; else a2 += rv2;
            nb += __shfl_xor_sync(0xffffffffu, nb, 1);
        }
        float fst = (sub & 1) ? a1 : a0;
        float snd = (sub & 1) ? a3 : a2;
        {
            float w  = (sub & 2) ? fst : snd;
            float rv = __shfl_xor_sync(0xffffffffu, w, 2);
            if (sub & 2) snd += rv; else fst += rv;
            nb += __shfl_xor_sync(0xffffffffu, nb, 2);
        }
        float dot = (sub & 2) ? snd : fst;
        dot += __shfl_xor_sync(0xffffffffu, dot, 4);
        nb  += __shfl_xor_sync(0xffffffffu, nb, 4);

        if (sub < 4) {
            float d2 = fmaf(-2.f, dot, naa + nb);
            d_s[sub][r] = sqrtf(fmaxf(d2, 0.f));     // clamp self-pair cancel
        }
        // roll the pipeline
        if (pass < 7) {
            #pragma unroll
            for (int i = 0; i < 4; i++) { vx[i] = nx[i]; vy[i] = ny[i]; }
        }
    }
    __syncthreads();

    // ---- compact positives: warp a compacts anchor a (ballot, fixed order) ----
    if (wid < APC) {
        const int a = wid, self = ib + a;
        int cnt = 0;
        #pragma unroll
        for (int base = 0; base < NN; base += 32) {
            int j = base + lane;
            bool p = same_s[a][j] && (j != self);
            unsigned msk = __ballot_sync(0xffffffffu, p);
            if (p) posd[a][cnt + __popc(msk & ((1u << lane) - 1u))] = d_s[a][j] + m;
            cnt += __popc(msk);
        }
        if (lane < 4) posd[a][cnt + lane] = -1e30f;  // sentinels: exact-0 relu
        if (lane == 0) np_s[a] = cnt;
    }
    __syncthreads();

    // ---- Phase B: thread owns candidate negative g = tid; packed f32x2,
    //      one LDS.128 per 4 positives ----
    const ull SMASK = 0x7FFFFFFF7FFFFFFFULL;
    const ull HALF2 = pack2(0.5f, 0.5f);
    ull acc2 = 0, acc2b = 0;
    #pragma unroll
    for (int a = 0; a < APC; a++) {
        const int npairs = (np_s[a] + 3) >> 2;   // 4 terms per iteration
        if (!same_s[a][tid]) {
            const float dg = d_s[a][tid];
            const ull  ndg2 = pack2(-dg, -dg);
            const ulonglong2* pv = (const ulonglong2*)&posd[a][0];
            for (int q = 0; q < npairs; q++) {
                ulonglong2 v = pv[q];            // LDS.128 broadcast
                ull t0 = add2(v.x, ndg2);
                ull t1 = add2(v.y, ndg2);
                ull r0 = add2(t0, t0 & SMASK);   // 2*relu, exact
                ull r1 = add2(t1, t1 & SMASK);
                fma2(acc2,  r0, HALF2);
                fma2(acc2b, r1, HALF2);
            }
        }
    }
    float acc = hsum2(acc2) + hsum2(acc2b);

    // ---- block reduce (fixed tree) ----
    #pragma unroll
    for (int o = 16; o > 0; o >>= 1) acc += __shfl_xor_sync(0xffffffffu, acc, o);
    if (lane == 0) wred[wid] = acc;
    __syncthreads();
    if (wid == 0) {
        float v = (lane < THREADS / 32) ? wred[lane] : 0.f;
        #pragma unroll
        for (int o = 8; o > 0; o >>= 1) v += __shfl_xor_sync(0xffffffffu, v, o);
        if (lane == 0) {
            g_partial[blockIdx.x] = v;
            float c = 0.f;
            #pragma unroll
            for (int a = 0; a < APC; a++)
                c += (float)np_s[a] * (float)(NN - 1 - np_s[a]);
            g_count[blockIdx.x] = c;
            __threadfence();
            int t = atomicAdd(&g_done, 1);
            flag_s = (t == NCTA - 1) ? 1 : 0;   // am I the last CTA?
        }
    }
    __syncthreads();

    // ---- last CTA: deterministic fp64 final reduction ----
    if (flag_s && wid == 0) {
        double sd = 0.0, sc = 0.0;
        for (int k = lane; k < NCTA; k += 32) {
            sd += (double)g_partial[k];
            sc += (double)g_count[k];
        }
        #pragma unroll
        for (int o = 16; o > 0; o >>= 1) {
            sd += __shfl_xor_sync(0xffffffffu, sd, o);
            sc += __shfl_xor_sync(0xffffffffu, sc, o);
        }
        if (lane == 0) {
            out[0] = (float)(sd / sc);
            for (int k = 1; k < out_size; k++) out[k] = 0.f;
            __threadfence();
            g_done = 0;   // reset for next graph replay
        }
    }
}

extern "C" void kernel_launch(void* const* d_in, const int* in_sizes, int n_in,
                              void* d_out, int out_size) {
    const float* x      = (const float*)d_in[0];
    const int*   labels = (const int*)d_in[1];
    const void*  margin = (n_in >= 3) ? d_in[2] : nullptr;

    fused_triplet_kernel<<<NCTA, THREADS>>>(x, labels, margin,
                                            (float*)d_out, out_size);
}

// round 16
// speedup vs baseline: 1.2027x; 1.0156x over previous
#include <cuda_runtime.h>

#define NN 512          // batch size
#define DD 128          // feature dim
#define THREADS 512
#define APC 4           // anchors per CTA
#define NCTA (NN / APC) // 128
#define NPOS (NN + 4)   // posd row + sentinel pad (516: 16B-aligned rows)
#define DPAD 520        // d_s row stride (8 mod 32) -> conflict-free stores

typedef unsigned long long ull;

__device__ float g_partial[NCTA];
__device__ float g_count[NCTA];
__device__ int   g_done = 0;   // reset by finalizing CTA each launch

// Margin scalar may arrive as float32 or float64 device scalar.
__device__ __forceinline__ float read_margin(const void* p) {
    if (p == nullptr) return 0.2f;
    float f = *(const float*)p;
    if (f == 0.0f) return 0.0f;
    float af = fabsf(f);
    if (af > 1e-20f && af < 1e6f) return f;
    return (float)(*(const double*)p);
}

// Packed f32x2 ops (Blackwell PTX).
__device__ __forceinline__ void fma2(ull& d, ull a, ull b) {
    asm("fma.rn.f32x2 %0, %1, %2, %0;" : "+l"(d) : "l"(a), "l"(b));
}
__device__ __forceinline__ ull add2(ull a, ull b) {
    ull r;
    asm("add.rn.f32x2 %0, %1, %2;" : "=l"(r) : "l"(a), "l"(b));
    return r;
}
__device__ __forceinline__ float hsum2(ull v) {
    float lo, hi;
    asm("mov.b64 {%0, %1}, %2;" : "=f"(lo), "=f"(hi) : "l"(v));
    return lo + hi;
}
__device__ __forceinline__ ull pack2(float lo, float hi) {
    ull r;
    asm("mov.b64 %0, {%1, %2};" : "=l"(r) : "f"(lo), "f"(hi));
    return r;
}

// ---------------------------------------------------------------------------
// One fused kernel = R13 (best measured, 16.42us) with:
//  - positive-INDEX compaction moved BEFORE Phase A (labels-only), run by
//    warps 0-3 while warps 4-15 start Phase A -> no idle-SMSP window
//  - posd filled in ONE parallel step after Phase A (1 LDS+ADD+STS / thread)
//  - Phase B exactly R13's LDS.64 packed relu (measured best form)
//  - merged packed accumulator tail (one hsum)
// CTA = 4 consecutive anchors, 512 threads.
// ---------------------------------------------------------------------------
__global__ void __launch_bounds__(THREADS, 1)
fused_triplet_kernel(const float* __restrict__ x, const int* __restrict__ L32,
                     const void* __restrict__ mp, float* __restrict__ out,
                     int out_size)
{
    __shared__ float                  d_s[APC][DPAD];   // distance rows (padded)
    __shared__ unsigned char          same_s[APC][NN];  // same-label flags, 2 KB
    __shared__ __align__(16) float    posd[APC][NPOS];  // compacted d[pos]+m
    __shared__ int                    pidx[APC][NN];    // positive row indices
    __shared__ int                    lab_s[NN];        // 2 KB
    __shared__ int                    np_s[APC];
    __shared__ float                  wred[THREADS / 32];
    __shared__ int                    flag_s;

    const int tid  = threadIdx.x;
    const int lane = tid & 31;
    const int wid  = tid >> 5;
    const int sub  = tid & 7;      // slice within 8-lane row group
    const int grp  = tid >> 3;     // row-group id 0..63
    const int ib   = blockIdx.x * APC;
    const float m  = read_margin(mp);

    // ---- label dtype detect (int64 => odd 32-bit words all zero) ----
    if (tid == 0) flag_s = 0;
    __syncthreads();
    if (tid < 256 && L32[2 * tid + 1] != 0) flag_s = 1;  // benign OR-race

    // ---- hoist anchors (+eps) into registers: 4 anchors x 4 float4 slices ----
    ull xw[APC][4][2];             // 64 registers of anchor data
    #pragma unroll
    for (int a = 0; a < APC; a++) {
        const float4* xa = (const float4*)(x + (ib + a) * DD);
        #pragma unroll
        for (int i = 0; i < 4; i++) {
            float4 w = xa[sub + 8 * i];
            xw[a][i][0] = pack2(w.x + 1e-6f, w.y + 1e-6f);
            xw[a][i][1] = pack2(w.z + 1e-6f, w.w + 1e-6f);
        }
    }
    // ---- anchor norms in-register (plain 8-lane butterfly, one-time) ----
    float na0, na1, na2, na3;
    {
        float nv[APC];
        #pragma unroll
        for (int a = 0; a < APC; a++) {
            ull nacc = 0;
            #pragma unroll
            for (int i = 0; i < 4; i++) {
                fma2(nacc, xw[a][i][0], xw[a][i][0]);
                fma2(nacc, xw[a][i][1], xw[a][i][1]);
            }
            float s = hsum2(nacc);
            #pragma unroll
            for (int o = 1; o <= 4; o <<= 1) s += __shfl_xor_sync(0xffffffffu, s, o);
            nv[a] = s;
        }
        na0 = nv[0]; na1 = nv[1]; na2 = nv[2]; na3 = nv[3];
    }

    __syncthreads();               // flag_s valid
    const int is64 = (flag_s == 0);
    lab_s[tid] = is64 ? L32[2 * tid] : L32[tid];
    __syncthreads();               // lab_s valid

    // ---- same-label flags once ----
    {
        int lj = lab_s[tid];
        same_s[0][tid] = (unsigned char)(lj == lab_s[ib + 0]);
        same_s[1][tid] = (unsigned char)(lj == lab_s[ib + 1]);
        same_s[2][tid] = (unsigned char)(lj == lab_s[ib + 2]);
        same_s[3][tid] = (unsigned char)(lj == lab_s[ib + 3]);
    }

    // ---- EARLY index compaction: warps 0-3 (labels only), while warps
    //      4-15 proceed into Phase A. Visibility covered by Phase A barrier.
    if (wid < APC) {
        const int a = wid, self = ib + a;
        const int Lw = lab_s[self];
        int cnt = 0;
        #pragma unroll
        for (int base = 0; base < NN; base += 32) {
            int j = base + lane;
            bool p = (lab_s[j] == Lw) && (j != self);
            unsigned msk = __ballot_sync(0xffffffffu, p);
            if (p) pidx[a][cnt + __popc(msk & ((1u << lane) - 1u))] = j;
            cnt += __popc(msk);
        }
        if (lane < 4) posd[a][cnt + lane] = -1e30f;  // sentinels: exact-0 relu
        if (lane == 0) np_s[a] = cnt;
    }

    // per-lane anchor norm for the distributed finalize (lane sub -> anchor sub&3)
    const float naa = ((sub & 3) == 0) ? na0 : ((sub & 3) == 1) ? na1
                    : ((sub & 3) == 2) ? na2 : na3;

    // ---- Phase A: pipelined; d^2 = na + nb - 2*dot; 8 passes x 64 rows ----
    ull vx[4], vy[4];              // current pass's row slice (prefetched)
    {
        const ulonglong2* xr = (const ulonglong2*)(x + grp * DD);
        #pragma unroll
        for (int i = 0; i < 4; i++) {
            ulonglong2 t = xr[sub + 8 * i];
            vx[i] = t.x; vy[i] = t.y;
        }
    }
    #pragma unroll
    for (int pass = 0; pass < 8; pass++) {
        const int r = pass * 64 + grp;
        // prefetch next pass FIRST (independent of this pass's math)
        ull nx[4], ny[4];
        if (pass < 7) {
            const ulonglong2* xn = (const ulonglong2*)(x + (r + 64) * DD);
            #pragma unroll
            for (int i = 0; i < 4; i++) {
                ulonglong2 t = xn[sub + 8 * i];
                nx[i] = t.x; ny[i] = t.y;
            }
        }
        // compute with current registers (covers the prefetch latency)
        ull nbp = 0, p0 = 0, p1 = 0, p2 = 0, p3 = 0;
        #pragma unroll
        for (int i = 0; i < 4; i++) {
            fma2(nbp, vx[i], vx[i]);       fma2(nbp, vy[i], vy[i]);
            fma2(p0, xw[0][i][0], vx[i]);  fma2(p0, xw[0][i][1], vy[i]);
            fma2(p1, xw[1][i][0], vx[i]);  fma2(p1, xw[1][i][1], vy[i]);
            fma2(p2, xw[2][i][0], vx[i]);  fma2(p2, xw[2][i][1], vy[i]);
            fma2(p3, xw[3][i][0], vx[i]);  fma2(p3, xw[3][i][1], vy[i]);
        }
        float nb = hsum2(nbp);
        float a0 = hsum2(p0), a1 = hsum2(p1), a2 = hsum2(p2), a3 = hsum2(p3);

        // value-pairing butterfly: 7 SHFL total
        {
            float w  = (sub & 1) ? a0 : a1;
            float rv = __shfl_xor_sync(0xffffffffu, w, 1);
            if (sub & 1) a1 += rv; else a0 += rv;
            float w2  = (sub & 1) ? a2 : a3;
            float rv2 = __shfl_xor_sync(0xffffffffu, w2, 1);
            if (sub & 1) a3 += rv2; else a2 += rv2;
            nb += __shfl_xor_sync(0xffffffffu, nb, 1);
        }
        float fst = (sub & 1) ? a1 : a0;
        float snd = (sub & 1) ? a3 : a2;
        {
            float w  = (sub & 2) ? fst : snd;
            float rv = __shfl_xor_sync(0xffffffffu, w, 2);
            if (sub & 2) snd += rv; else fst += rv;
            nb += __shfl_xor_sync(0xffffffffu, nb, 2);
        }
        float dot = (sub & 2) ? snd : fst;
        dot += __shfl_xor_sync(0xffffffffu, dot, 4);
        nb  += __shfl_xor_sync(0xffffffffu, nb, 4);

        if (sub < 4) {
            float d2 = fmaf(-2.f, dot, naa + nb);
            d_s[sub][r] = sqrtf(fmaxf(d2, 0.f));     // clamp self-pair cancel
        }
        // roll the pipeline
        if (pass < 7) {
            #pragma unroll
            for (int i = 0; i < 4; i++) { vx[i] = nx[i]; vy[i] = ny[i]; }
        }
    }
    __syncthreads();               // d_s, pidx, np_s all valid

    // ---- one-shot posd fill: thread f < P gathers its positive's distance ----
    const int np0 = np_s[0], np1 = np_s[1], np2 = np_s[2], np3 = np_s[3];
    {
        const int c1 = np0, c2 = c1 + np1, c3 = c2 + np2, P = c3 + np3;
        if (tid < P) {
            int a = (tid >= c1) + (tid >= c2) + (tid >= c3);
            int k = tid - ((a == 0) ? 0 : (a == 1) ? c1 : (a == 2) ? c2 : c3);
            int j = pidx[a][k];
            posd[a][k] = d_s[a][j] + m;
        }
    }
    __syncthreads();               // posd valid

    // ---- Phase B: thread owns candidate negative g = tid; packed f32x2 ----
    const ull SMASK = 0x7FFFFFFF7FFFFFFFULL;
    const ull HALF2 = pack2(0.5f, 0.5f);
    ull acc2 = 0, acc2b = 0;
    #pragma unroll
    for (int a = 0; a < APC; a++) {
        const int np = (a == 0) ? np0 : (a == 1) ? np1 : (a == 2) ? np2 : np3;
        const int npairs = (np + 3) >> 2;        // 4 terms per iteration
        if (!same_s[a][tid]) {
            const float dg = d_s[a][tid];
            const ull  ndg2 = pack2(-dg, -dg);
            const ull* pv = (const ull*)&posd[a][0];
            for (int q = 0; q < npairs; q++) {
                ull w0 = pv[2 * q];
                ull w1 = pv[2 * q + 1];
                ull t0 = add2(w0, ndg2);
                ull t1 = add2(w1, ndg2);
                ull r0 = add2(t0, t0 & SMASK);   // 2*relu, exact
                ull r1 = add2(t1, t1 & SMASK);
                fma2(acc2,  r0, HALF2);
                fma2(acc2b, r1, HALF2);
            }
        }
    }
    float acc = hsum2(add2(acc2, acc2b));        // merged packed tail

    // ---- block reduce (fixed tree) ----
    #pragma unroll
    for (int o = 16; o > 0; o >>= 1) acc += __shfl_xor_sync(0xffffffffu, acc, o);
    if (lane == 0) wred[wid] = acc;
    __syncthreads();
    if (wid == 0) {
        float v = (lane < THREADS / 32) ? wred[lane] : 0.f;
        #pragma unroll
        for (int o = 8; o > 0; o >>= 1) v += __shfl_xor_sync(0xffffffffu, v, o);
        if (lane == 0) {
            g_partial[blockIdx.x] = v;
            float c = (float)np0 * (float)(NN - 1 - np0)
                    + (float)np1 * (float)(NN - 1 - np1)
                    + (float)np2 * (float)(NN - 1 - np2)
                    + (float)np3 * (float)(NN - 1 - np3);
            g_count[blockIdx.x] = c;
            __threadfence();
            int t = atomicAdd(&g_done, 1);
            flag_s = (t == NCTA - 1) ? 1 : 0;   // am I the last CTA?
        }
    }
    __syncthreads();

    // ---- last CTA: deterministic fp64 final reduction ----
    if (flag_s && wid == 0) {
        double sd = 0.0, sc = 0.0;
        for (int k = lane; k < NCTA; k += 32) {
            sd += (double)g_partial[k];
            sc += (double)g_count[k];
        }
        #pragma unroll
        for (int o = 16; o > 0; o >>= 1) {
            sd += __shfl_xor_sync(0xffffffffu, sd, o);
            sc += __shfl_xor_sync(0xffffffffu, sc, o);
        }
        if (lane == 0) {
            out[0] = (float)(sd / sc);
            for (int k = 1; k < out_size; k++) out[k] = 0.f;
            __threadfence();
            g_done = 0;   // reset for next graph replay
        }
    }
}

extern "C" void kernel_launch(void* const* d_in, const int* in_sizes, int n_in,
                              void* d_out, int out_size) {
    const float* x      = (const float*)d_in[0];
    const int*   labels = (const int*)d_in[1];
    const void*  margin = (n_in >= 3) ? d_in[2] : nullptr;

    fused_triplet_kernel<<<NCTA, THREADS>>>(x, labels, margin,
                                            (float*)d_out, out_size);
}

// round 17
// speedup vs baseline: 1.2051x; 1.0020x over previous
#include <cuda_runtime.h>

#define NN 512          // batch size
#define DD 128          // feature dim
#define THREADS 512
#define APC 4           // anchors per CTA
#define NCTA (NN / APC) // 128
#define NPOS (NN + 4)   // posd row + sentinel pad (516: 16B-aligned rows)
#define DPAD 520        // d_s row stride (8 mod 32) -> conflict-free stores

typedef unsigned long long ull;

__device__ float g_partial[NCTA];
__device__ float g_count[NCTA];
__device__ int   g_done = 0;   // reset by finalizing CTA each launch

// Margin scalar may arrive as float32 or float64 device scalar.
__device__ __forceinline__ float read_margin(const void* p) {
    if (p == nullptr) return 0.2f;
    float f = *(const float*)p;
    if (f == 0.0f) return 0.0f;
    float af = fabsf(f);
    if (af > 1e-20f && af < 1e6f) return f;
    return (float)(*(const double*)p);
}

// Packed f32x2 ops (Blackwell PTX).
__device__ __forceinline__ void fma2(ull& d, ull a, ull b) {
    asm("fma.rn.f32x2 %0, %1, %2, %0;" : "+l"(d) : "l"(a), "l"(b));
}
__device__ __forceinline__ ull add2(ull a, ull b) {
    ull r;
    asm("add.rn.f32x2 %0, %1, %2;" : "=l"(r) : "l"(a), "l"(b));
    return r;
}
__device__ __forceinline__ float hsum2(ull v) {
    float lo, hi;
    asm("mov.b64 {%0, %1}, %2;" : "=f"(lo), "=f"(hi) : "l"(v));
    return lo + hi;
}
__device__ __forceinline__ ull pack2(float lo, float hi) {
    ull r;
    asm("mov.b64 %0, {%1, %2};" : "=l"(r) : "f"(lo), "f"(hi));
    return r;
}

// ---------------------------------------------------------------------------
// One fused kernel = R13 (ncu-best, 15.68us) minus two CTA barriers:
//  - label dtype detected PER-WARP via ballot over 32 probe words
//    (L32[2*(tid&255)+1]; in-bounds for int32 and int64; for int32 the
//    probability a warp sees 32 zero labels is 16^-32 -> per-warp safe)
//  - merged packed Phase-B accumulator tail (one hsum)
// Phase A: pipelined Gram-identity rows; anchors in registers; 7-SHFL
//          value-pairing butterfly; lane-parallel sqrt+store finalize.
// Phase B: packed f32x2 relu over sentinel-padded compacted positives.
// Last-arriving CTA does the deterministic fp64 final reduction.
// CTA = 4 consecutive anchors, 512 threads.
// ---------------------------------------------------------------------------
__global__ void __launch_bounds__(THREADS, 1)
fused_triplet_kernel(const float* __restrict__ x, const int* __restrict__ L32,
                     const void* __restrict__ mp, float* __restrict__ out,
                     int out_size)
{
    __shared__ float                  d_s[APC][DPAD];   // distance rows (padded)
    __shared__ unsigned char          same_s[APC][NN];  // same-label flags, 2 KB
    __shared__ __align__(16) float    posd[APC][NPOS];  // compacted d[pos]+m
    __shared__ int                    lab_s[NN];        // 2 KB
    __shared__ int                    np_s[APC];
    __shared__ float                  wred[THREADS / 32];
    __shared__ int                    flag_s;           // "last CTA" flag only

    const int tid  = threadIdx.x;
    const int lane = tid & 31;
    const int wid  = tid >> 5;
    const int sub  = tid & 7;      // slice within 8-lane row group
    const int grp  = tid >> 3;     // row-group id 0..63
    const int ib   = blockIdx.x * APC;
    const float m  = read_margin(mp);

    // ---- per-warp label dtype detect: int64 => probed high words all zero.
    //      Probe index 2*(tid&255)+1 <= 511 is in-bounds for both dtypes.
    unsigned bal = __ballot_sync(0xffffffffu, L32[2 * (tid & 255) + 1] != 0);
    const int is64 = (bal == 0);
    lab_s[tid] = is64 ? L32[2 * tid] : L32[tid];

    // ---- hoist anchors (+eps) into registers: 4 anchors x 4 float4 slices ----
    ull xw[APC][4][2];             // 64 registers of anchor data
    #pragma unroll
    for (int a = 0; a < APC; a++) {
        const float4* xa = (const float4*)(x + (ib + a) * DD);
        #pragma unroll
        for (int i = 0; i < 4; i++) {
            float4 w = xa[sub + 8 * i];
            xw[a][i][0] = pack2(w.x + 1e-6f, w.y + 1e-6f);
            xw[a][i][1] = pack2(w.z + 1e-6f, w.w + 1e-6f);
        }
    }
    // ---- anchor norms in-register (plain 8-lane butterfly, one-time) ----
    float na0, na1, na2, na3;
    {
        float nv[APC];
        #pragma unroll
        for (int a = 0; a < APC; a++) {
            ull nacc = 0;
            #pragma unroll
            for (int i = 0; i < 4; i++) {
                fma2(nacc, xw[a][i][0], xw[a][i][0]);
                fma2(nacc, xw[a][i][1], xw[a][i][1]);
            }
            float s = hsum2(nacc);
            #pragma unroll
            for (int o = 1; o <= 4; o <<= 1) s += __shfl_xor_sync(0xffffffffu, s, o);
            nv[a] = s;
        }
        na0 = nv[0]; na1 = nv[1]; na2 = nv[2]; na3 = nv[3];
    }

    __syncthreads();               // lab_s valid (single early barrier)

    // ---- same-label flags once (hoisted out of the pass loop) ----
    {
        int lj = lab_s[tid];
        same_s[0][tid] = (unsigned char)(lj == lab_s[ib + 0]);
        same_s[1][tid] = (unsigned char)(lj == lab_s[ib + 1]);
        same_s[2][tid] = (unsigned char)(lj == lab_s[ib + 2]);
        same_s[3][tid] = (unsigned char)(lj == lab_s[ib + 3]);
    }

    // per-lane anchor norm for the distributed finalize (lane sub -> anchor sub&3)
    const float naa = ((sub & 3) == 0) ? na0 : ((sub & 3) == 1) ? na1
                    : ((sub & 3) == 2) ? na2 : na3;

    // ---- Phase A: pipelined; d^2 = na + nb - 2*dot; 8 passes x 64 rows ----
    ull vx[4], vy[4];              // current pass's row slice (prefetched)
    {
        const ulonglong2* xr = (const ulonglong2*)(x + grp * DD);
        #pragma unroll
        for (int i = 0; i < 4; i++) {
            ulonglong2 t = xr[sub + 8 * i];
            vx[i] = t.x; vy[i] = t.y;
        }
    }
    #pragma unroll
    for (int pass = 0; pass < 8; pass++) {
        const int r = pass * 64 + grp;
        // prefetch next pass FIRST (independent of this pass's math)
        ull nx[4], ny[4];
        if (pass < 7) {
            const ulonglong2* xn = (const ulonglong2*)(x + (r + 64) * DD);
            #pragma unroll
            for (int i = 0; i < 4; i++) {
                ulonglong2 t = xn[sub + 8 * i];
                nx[i] = t.x; ny[i] = t.y;
            }
        }
        // compute with current registers (covers the prefetch latency)
        ull nbp = 0, p0 = 0, p1 = 0, p2 = 0, p3 = 0;
        #pragma unroll
        for (int i = 0; i < 4; i++) {
            fma2(nbp, vx[i], vx[i]);       fma2(nbp, vy[i], vy[i]);
            fma2(p0, xw[0][i][0], vx[i]);  fma2(p0, xw[0][i][1], vy[i]);
            fma2(p1, xw[1][i][0], vx[i]);  fma2(p1, xw[1][i][1], vy[i]);
            fma2(p2, xw[2][i][0], vx[i]);  fma2(p2, xw[2][i][1], vy[i]);
            fma2(p3, xw[3][i][0], vx[i]);  fma2(p3, xw[3][i][1], vy[i]);
        }
        float nb = hsum2(nbp);
        float a0 = hsum2(p0), a1 = hsum2(p1), a2 = hsum2(p2), a3 = hsum2(p3);

        // value-pairing butterfly: 7 SHFL total
        {
            float w  = (sub & 1) ? a0 : a1;
            float rv = __shfl_xor_sync(0xffffffffu, w, 1);
            if (sub & 1) a1 += rv; else a0 += rv;
            float w2  = (sub & 1) ? a2 : a3;
            float rv2 = __shfl_xor_sync(0xffffffffu, w2, 1);
            if (sub & 1) a3 += rv2; else a2 += rv2;
            nb += __shfl_xor_sync(0xffffffffu, nb, 1);
        }
        float fst = (sub & 1) ? a1 : a0;
        float snd = (sub & 1) ? a3 : a2;
        {
            float w  = (sub & 2) ? fst : snd;
            float rv = __shfl_xor_sync(0xffffffffu, w, 2);
            if (sub & 2) snd += rv; else fst += rv;
            nb += __shfl_xor_sync(0xffffffffu, nb, 2);
        }
        float dot = (sub & 2) ? snd : fst;
        dot += __shfl_xor_sync(0xffffffffu, dot, 4);
        nb  += __shfl_xor_sync(0xffffffffu, nb, 4);

        if (sub < 4) {
            float d2 = fmaf(-2.f, dot, naa + nb);
            d_s[sub][r] = sqrtf(fmaxf(d2, 0.f));     // clamp self-pair cancel
        }
        // roll the pipeline
        if (pass < 7) {
            #pragma unroll
            for (int i = 0; i < 4; i++) { vx[i] = nx[i]; vy[i] = ny[i]; }
        }
    }
    __syncthreads();

    // ---- compact positives: warp a compacts anchor a (ballot, fixed order) ----
    if (wid < APC) {
        const int a = wid, self = ib + a;
        int cnt = 0;
        #pragma unroll
        for (int base = 0; base < NN; base += 32) {
            int j = base + lane;
            bool p = same_s[a][j] && (j != self);
            unsigned msk = __ballot_sync(0xffffffffu, p);
            if (p) posd[a][cnt + __popc(msk & ((1u << lane) - 1u))] = d_s[a][j] + m;
            cnt += __popc(msk);
        }
        if (lane < 4) posd[a][cnt + lane] = -1e30f;  // sentinels: exact-0 relu
        if (lane == 0) np_s[a] = cnt;
    }
    __syncthreads();

    // ---- Phase B: thread owns candidate negative g = tid; packed f32x2 ----
    const ull SMASK = 0x7FFFFFFF7FFFFFFFULL;
    const ull HALF2 = pack2(0.5f, 0.5f);
    ull acc2 = 0, acc2b = 0;
    #pragma unroll
    for (int a = 0; a < APC; a++) {
        const int npairs = (np_s[a] + 3) >> 2;   // 4 terms per iteration
        if (!same_s[a][tid]) {
            const float dg = d_s[a][tid];
            const ull  ndg2 = pack2(-dg, -dg);
            const ull* pv = (const ull*)&posd[a][0];
            for (int q = 0; q < npairs; q++) {
                ull w0 = pv[2 * q];
                ull w1 = pv[2 * q + 1];
                ull t0 = add2(w0, ndg2);
                ull t1 = add2(w1, ndg2);
                ull r0 = add2(t0, t0 & SMASK);   // 2*relu, exact
                ull r1 = add2(t1, t1 & SMASK);
                fma2(acc2,  r0, HALF2);
                fma2(acc2b, r1, HALF2);
            }
        }
    }
    float acc = hsum2(add2(acc2, acc2b));        // merged packed tail

    // ---- block reduce (fixed tree) ----
    #pragma unroll
    for (int o = 16; o > 0; o >>= 1) acc += __shfl_xor_sync(0xffffffffu, acc, o);
    if (lane == 0) wred[wid] = acc;
    __syncthreads();
    if (wid == 0) {
        float v = (lane < THREADS / 32) ? wred[lane] : 0.f;
        #pragma unroll
        for (int o = 8; o > 0; o >>= 1) v += __shfl_xor_sync(0xffffffffu, v, o);
        if (lane == 0) {
            g_partial[blockIdx.x] = v;
            float c = 0.f;
            #pragma unroll
            for (int a = 0; a < APC; a++)
                c += (float)np_s[a] * (float)(NN - 1 - np_s[a]);
            g_count[blockIdx.x] = c;
            __threadfence();
            int t = atomicAdd(&g_done, 1);
            flag_s = (t == NCTA - 1) ? 1 : 0;   // am I the last CTA?
        }
    }
    __syncthreads();

    // ---- last CTA: deterministic fp64 final reduction ----
    if (flag_s && wid == 0) {
        double sd = 0.0, sc = 0.0;
        for (int k = lane; k < NCTA; k += 32) {
            sd += (double)g_partial[k];
            sc += (double)g_count[k];
        }
        #pragma unroll
        for (int o = 16; o > 0; o >>= 1) {
            sd += __shfl_xor_sync(0xffffffffu, sd, o);
            sc += __shfl_xor_sync(0xffffffffu, sc, o);
        }
        if (lane == 0) {
            out[0] = (float)(sd / sc);
            for (int k = 1; k < out_size; k++) out[k] = 0.f;
            __threadfence();
            g_done = 0;   // reset for next graph replay
        }
    }
}

extern "C" void kernel_launch(void* const* d_in, const int* in_sizes, int n_in,
                              void* d_out, int out_size) {
    const float* x      = (const float*)d_in[0];
    const int*   labels = (const int*)d_in[1];
    const void*  margin = (n_in >= 3) ? d_in[2] : nullptr;

    fused_triplet_kernel<<<NCTA, THREADS>>>(x, labels, margin,
                                            (float*)d_out, out_size);
}